// round 13
// baseline (speedup 1.0000x reference)
#include <cuda_runtime.h>
#include <cuda_fp16.h>
#include <math.h>

#define NN 50000
#define NNP 50048
#define EE 800000
#define SSED 8192
#define HD 64

// ---------------- scratch (device globals) ----------------------------------
__device__ int    g_off[3][NN + 1];
__device__ int    g_cur[3 * NN];        // zero-initialized; self-restoring per call
__device__ int    g_esrc[3][EE];
__device__ __half g_xh[NN * HD];
__device__ float  g_S[NNP * 192];
__device__ float  g_h1[NNP * HD];
__device__ float  g_h2[SSED * HD];
__device__ __half g_hsh[SSED * HD];
__device__ float  g_zd2[3 * SSED * 32];
__device__ __half g_y1h[3 * SSED * 256];
__device__ __half g_y2h[3 * SSED * 2048];
__device__ __half g_wd1h[3 * 64 * 256];
__device__ __half g_wd2h[3 * 256 * 32];
__device__ __half g_wf1h[3 * 64 * 256];
__device__ __half g_wf2h[3 * 256 * 2048];
__device__ __half g_wf3h[3 * 2048 * 320];

// ---------------- fused conversion + degree count ----------------------------
#define CVT_XN (NN * HD)
#define CVT_D1 (3 * 64 * 256)
#define CVT_D2 (3 * 256 * 32)
#define CVT_F1 (3 * 64 * 256)
#define CVT_F2 (3 * 256 * 2048)
#define CVT_F3 (3 * 2048 * 320)
#define CVT_TOT ((long)CVT_XN + CVT_D1 + CVT_D2 + CVT_F1 + CVT_F2 + CVT_F3 + 3L * EE)

// g_cur must be zero on entry (static init on call 1; k_gather_h re-zeroes each call)
__global__ void k_convert(const float* __restrict__ x, const float* __restrict__ dW1,
                          const float* __restrict__ dW2, const float* __restrict__ fW1,
                          const float* __restrict__ fW2, const float* __restrict__ fW3,
                          const int* __restrict__ d0, const int* __restrict__ d1,
                          const int* __restrict__ d2) {
    long i = (long)blockIdx.x * blockDim.x + threadIdx.x;
    if (i >= CVT_TOT) return;
    long j = i;
    if (j < CVT_XN) { g_xh[j] = __float2half_rn(x[j]); return; }
    j -= CVT_XN;
    if (j < CVT_D1) { g_wd1h[j] = __float2half_rn(dW1[j]); return; }
    j -= CVT_D1;
    if (j < CVT_D2) { g_wd2h[j] = __float2half_rn(dW2[j]); return; }
    j -= CVT_D2;
    if (j < CVT_F1) { g_wf1h[j] = __float2half_rn(fW1[j]); return; }
    j -= CVT_F1;
    if (j < CVT_F2) { g_wf2h[j] = __float2half_rn(fW2[j]); return; }
    j -= CVT_F2;
    if (j < CVT_F3) { g_wf3h[j] = __float2half_rn(fW3[j]); return; }
    j -= CVT_F3;
    // degree counting
    int r = (int)(j / EE);
    int e = (int)(j % EE);
    const int* d = (r == 0) ? d0 : ((r == 1) ? d1 : d2);
    atomicAdd(&g_cur[r * NN + d[e]], 1);
}

// ---------------- CSR scan + fill --------------------------------------------
__global__ void k_scan() {
    const int r = blockIdx.x;
    const int tid = threadIdx.x;
    __shared__ int sm[1024];
    const int CH = 49;
    int t0 = tid * CH;
    int t1 = t0 + CH; if (t1 > NN) t1 = NN;
    int sum = 0;
    for (int i = t0; i < t1; i++) sum += g_cur[r * NN + i];
    sm[tid] = sum;
    __syncthreads();
#pragma unroll
    for (int o = 1; o < 1024; o <<= 1) {
        int v = (tid >= o) ? sm[tid - o] : 0;
        __syncthreads();
        sm[tid] += v;
        __syncthreads();
    }
    int run = sm[tid] - sum;
    for (int i = t0; i < t1; i++) {
        int c = g_cur[r * NN + i];
        g_off[r][i] = run;
        run += c;
        g_cur[r * NN + i] = 0;          // reset for fill cursors
    }
    if (tid == 1023) g_off[r][NN] = run;
}

__global__ void k_fill(const int* __restrict__ s0, const int* __restrict__ d0,
                       const int* __restrict__ s1, const int* __restrict__ d1,
                       const int* __restrict__ s2, const int* __restrict__ d2) {
    const int r = blockIdx.y;
    const int* s = (r == 0) ? s0 : ((r == 1) ? s1 : s2);
    const int* d = (r == 0) ? d0 : ((r == 1) ? d1 : d2);
    int e = blockIdx.x * blockDim.x + threadIdx.x;
    if (e < EE) {
        int dv = d[e];
        int pos = g_off[r][dv] + atomicAdd(&g_cur[r * NN + dv], 1);
        g_esrc[r][pos] = s[e];
    }
}

// ---------------- gathers ----------------------------------------------------
__device__ __forceinline__ void addh8(float* a, uint4 v) {
    const __half2* hv = (const __half2*)&v;
#pragma unroll
    for (int k = 0; k < 4; k++) {
        float2 f = __half22float2(hv[k]);
        a[2 * k] += f.x;
        a[2 * k + 1] += f.y;
    }
}

// layer-1 gather fp16: 16 thr/node = two 8-lane groups splitting the edge list.
// Also re-zeroes g_cur (post-fill) so next call's k_convert counts from zero.
__global__ void k_gather_h(const __half* __restrict__ h) {
    const int r = blockIdx.y;
    const int t = threadIdx.x;
    int node = blockIdx.x * 16 + (t >> 4);
    if (node >= NN) return;
    if ((t & 15) == 0) g_cur[r * NN + node] = 0;
    const int sub = (t >> 3) & 1;
    const int q = (t & 7) << 3;
    const int b = g_off[r][node], e2 = g_off[r][node + 1];
    const int cnt = e2 - b;
    const int half = (cnt + 1) >> 1;
    const int gb = b + sub * half;
    const int ge = sub ? e2 : b + half;
    const int* es = g_esrc[r];
    float a0[8] = {0,0,0,0,0,0,0,0}, a1[8] = {0,0,0,0,0,0,0,0};
    float a2[8] = {0,0,0,0,0,0,0,0}, a3[8] = {0,0,0,0,0,0,0,0};
    int i = gb;
    for (; i + 4 <= ge; i += 4) {
        int s0 = __ldg(es + i), s1 = __ldg(es + i + 1);
        int s2 = __ldg(es + i + 2), s3 = __ldg(es + i + 3);
        uint4 v0 = *(const uint4*)(h + (long)s0 * HD + q);
        uint4 v1 = *(const uint4*)(h + (long)s1 * HD + q);
        uint4 v2 = *(const uint4*)(h + (long)s2 * HD + q);
        uint4 v3 = *(const uint4*)(h + (long)s3 * HD + q);
        addh8(a0, v0); addh8(a1, v1); addh8(a2, v2); addh8(a3, v3);
    }
    for (; i < ge; i++) {
        uint4 v = *(const uint4*)(h + (long)__ldg(es + i) * HD + q);
        addh8(a0, v);
    }
    float inv = (cnt > 0) ? 1.f / (float)cnt : 1.f;
#pragma unroll
    for (int k = 0; k < 8; k++) {
        float v = a0[k] + a1[k] + a2[k] + a3[k];
        v += __shfl_xor_sync(0xffffffffu, v, 8);
        a0[k] = v * inv;
    }
    if (sub == 0) {
        float* dst = g_S + (long)node * 192 + r * HD + q;
        *(float4*)dst = make_float4(a0[0], a0[1], a0[2], a0[3]);
        *(float4*)(dst + 4) = make_float4(a0[4], a0[5], a0[6], a0[7]);
    }
}

// layer-2 gather from fp32 h1: 16 thr per node, MLP=4
__global__ void k_gather(const float* __restrict__ h, int nLimit) {
    const int r = blockIdx.y;
    int node = blockIdx.x * 16 + (threadIdx.x >> 4);
    if (node >= nLimit) return;
    const int q = (threadIdx.x & 15) << 2;
    const int b = g_off[r][node], e2 = g_off[r][node + 1];
    const int* es = g_esrc[r];
    float4 a0 = make_float4(0.f, 0.f, 0.f, 0.f);
    float4 a1 = a0, a2 = a0, a3 = a0;
    int i = b;
    for (; i + 4 <= e2; i += 4) {
        int s0 = __ldg(es + i), s1 = __ldg(es + i + 1);
        int s2 = __ldg(es + i + 2), s3 = __ldg(es + i + 3);
        float4 v0 = *(const float4*)(h + (long)s0 * HD + q);
        float4 v1 = *(const float4*)(h + (long)s1 * HD + q);
        float4 v2 = *(const float4*)(h + (long)s2 * HD + q);
        float4 v3 = *(const float4*)(h + (long)s3 * HD + q);
        a0.x += v0.x; a0.y += v0.y; a0.z += v0.z; a0.w += v0.w;
        a1.x += v1.x; a1.y += v1.y; a1.z += v1.z; a1.w += v1.w;
        a2.x += v2.x; a2.y += v2.y; a2.z += v2.z; a2.w += v2.w;
        a3.x += v3.x; a3.y += v3.y; a3.z += v3.z; a3.w += v3.w;
    }
    for (; i < e2; i++) {
        float4 v = *(const float4*)(h + (long)__ldg(es + i) * HD + q);
        a0.x += v.x; a0.y += v.y; a0.z += v.z; a0.w += v.w;
    }
    a0.x += a1.x + a2.x + a3.x;
    a0.y += a1.y + a2.y + a3.y;
    a0.z += a1.z + a2.z + a3.z;
    a0.w += a1.w + a2.w + a3.w;
    float inv = (e2 > b) ? 1.f / (float)(e2 - b) : 1.f;
    a0.x *= inv; a0.y *= inv; a0.z *= inv; a0.w *= inv;
    *(float4*)(g_S + (long)node * 192 + r * HD + q) = a0;
}

__global__ void k_final(const float* __restrict__ W, const float* __restrict__ bias,
                        const float* __restrict__ noise) {
    __shared__ float sW[HD * HD];
    __shared__ float sS[4 * HD];
    for (int i = threadIdx.x; i < HD * HD; i += blockDim.x) sW[i] = W[i];
    __syncthreads();
    const int j = threadIdx.x & 63;
    const int ln = threadIdx.x >> 6;
    for (int n0 = blockIdx.x * 4; n0 < SSED; n0 += gridDim.x * 4) {
        int n = n0 + ln;
        sS[ln * HD + j] = g_h2[(long)n * HD + j];
        __syncthreads();
        float acc = bias[j];
#pragma unroll
        for (int k = 0; k < HD; k++)
            acc = fmaf(sS[ln * HD + k], sW[k * HD + j], acc);
        float v = (acc > 0.f) ? acc : 0.01f * acc;
        g_hsh[(long)n * HD + j] = __float2half_rn(v + noise[(long)n * HD + j]);
        __syncthreads();
    }
}

// ---------------- common asm helpers ----------------------------------------
__device__ __forceinline__ void cp16(void* smem, const void* gmem, bool valid) {
    unsigned s = (unsigned)__cvta_generic_to_shared(smem);
    int sz = valid ? 16 : 0;
    asm volatile("cp.async.cg.shared.global [%0], [%1], 16, %2;"
                 :: "r"(s), "l"(gmem), "r"(sz) : "memory");
}
__device__ __forceinline__ unsigned tf32(float f) {
    unsigned u;
    asm("cvt.rna.tf32.f32 %0, %1;" : "=r"(u) : "f"(f));
    return u;
}
__device__ __forceinline__ void mma8(float* c, const unsigned* a, const unsigned* b) {
    asm volatile("mma.sync.aligned.m16n8k8.row.col.f32.tf32.tf32.f32 "
                 "{%0,%1,%2,%3}, {%4,%5,%6,%7}, {%8,%9}, {%0,%1,%2,%3};"
                 : "+f"(c[0]), "+f"(c[1]), "+f"(c[2]), "+f"(c[3])
                 : "r"(a[0]), "r"(a[1]), "r"(a[2]), "r"(a[3]), "r"(b[0]), "r"(b[1]));
}
__device__ __forceinline__ void mma16h(float* c, const unsigned* a, const unsigned* b) {
    asm volatile("mma.sync.aligned.m16n8k16.row.col.f32.f16.f16.f32 "
                 "{%0,%1,%2,%3}, {%4,%5,%6,%7}, {%8,%9}, {%0,%1,%2,%3};"
                 : "+f"(c[0]), "+f"(c[1]), "+f"(c[2]), "+f"(c[3])
                 : "r"(a[0]), "r"(a[1]), "r"(a[2]), "r"(a[3]), "r"(b[0]), "r"(b[1]));
}
__device__ __forceinline__ void ldsm_x4(unsigned& r0, unsigned& r1, unsigned& r2,
                                        unsigned& r3, const void* p) {
    unsigned a = (unsigned)__cvta_generic_to_shared(p);
    asm volatile("ldmatrix.sync.aligned.m8n8.x4.shared.b16 {%0,%1,%2,%3}, [%4];"
                 : "=r"(r0), "=r"(r1), "=r"(r2), "=r"(r3) : "r"(a));
}
__device__ __forceinline__ void ldsm_x4t(unsigned& r0, unsigned& r1, unsigned& r2,
                                         unsigned& r3, const void* p) {
    unsigned a = (unsigned)__cvta_generic_to_shared(p);
    asm volatile("ldmatrix.sync.aligned.m8n8.x4.trans.shared.b16 {%0,%1,%2,%3}, [%4];"
                 : "=r"(r0), "=r"(r1), "=r"(r2), "=r"(r3) : "r"(a));
}

// ---------------- fp16 tensor-core GEMM (128x128 CTA, 64x32 warp, BK=32) ----
template <int ACT, int HOUT>
__global__ void __launch_bounds__(256, 2)
k_hgemm(const __half* __restrict__ Aall, const __half* __restrict__ Ball,
        const float* __restrict__ biasAll, void* __restrict__ Call,
        int M, int N, int K, long sA, long sB, long sBias, long sC, int ldc) {
    const int r = blockIdx.z;
    const __half* A = Aall + (long)r * sA;
    const __half* B = Ball + (long)r * sB;
    const float* bias = biasAll + (long)r * sBias;

    __shared__ __half As[2][128][40];
    __shared__ __half Bs[2][32][136];

    const int t = threadIdx.x;
    const int lane = t & 31;
    const int warp = t >> 5;
    const int wm = (warp >> 2) * 64;
    const int wn = (warp & 3) * 32;
    const long bm = (long)blockIdx.y * 128;
    const int bn = blockIdx.x * 128;

    const int aRow = t >> 1;
    const int aCol = (t & 1) << 4;
    const int bRow = t >> 3;
    const int bCol = (t & 7) << 4;
    const bool bv0 = (bn + bCol) < N;
    const bool bv1 = (bn + bCol + 8) < N;
    const int bc0 = bv0 ? bn + bCol : 0;
    const int bc1 = bv1 ? bn + bCol + 8 : 0;

    const int gid = lane >> 2;
    const int tig = lane & 3;

    float acc[4][4][4];
#pragma unroll
    for (int i = 0; i < 4; i++)
#pragma unroll
        for (int j = 0; j < 4; j++)
#pragma unroll
            for (int c = 0; c < 4; c++) acc[i][j][c] = 0.f;

    const int KT = K / 32;

    {
        cp16(&As[0][aRow][aCol], A + (bm + aRow) * (long)K + aCol, true);
        cp16(&As[0][aRow][aCol + 8], A + (bm + aRow) * (long)K + aCol + 8, true);
        cp16(&Bs[0][bRow][bCol], B + (long)bRow * N + bc0, bv0);
        cp16(&Bs[0][bRow][bCol + 8], B + (long)bRow * N + bc1, bv1);
        asm volatile("cp.async.commit_group;" ::: "memory");
        asm volatile("cp.async.wait_group 0;" ::: "memory");
        __syncthreads();
    }

    const int aFragRow = lane & 15;
    const int aFragCol = (lane >> 4) << 3;
    const int bFragRow = lane & 15;
    const int bFragCol = (lane >> 4) << 3;

    for (int kt = 0; kt < KT; kt++) {
        const int cb = kt & 1, nb = (kt + 1) & 1;
        if (kt + 1 < KT) {
            long ko = (long)(kt + 1) * 32;
            cp16(&As[nb][aRow][aCol], A + (bm + aRow) * (long)K + ko + aCol, true);
            cp16(&As[nb][aRow][aCol + 8], A + (bm + aRow) * (long)K + ko + aCol + 8, true);
            cp16(&Bs[nb][bRow][bCol], B + (ko + bRow) * (long)N + bc0, bv0);
            cp16(&Bs[nb][bRow][bCol + 8], B + (ko + bRow) * (long)N + bc1, bv1);
            asm volatile("cp.async.commit_group;" ::: "memory");
        }
#pragma unroll
        for (int kk = 0; kk < 2; kk++) {
            const int k0 = kk * 16;
            unsigned a[4][4], b[4][2];
#pragma unroll
            for (int tm = 0; tm < 4; tm++)
                ldsm_x4(a[tm][0], a[tm][1], a[tm][2], a[tm][3],
                        &As[cb][wm + tm * 16 + aFragRow][k0 + aFragCol]);
#pragma unroll
            for (int tn2 = 0; tn2 < 2; tn2++)
                ldsm_x4t(b[tn2 * 2][0], b[tn2 * 2][1], b[tn2 * 2 + 1][0], b[tn2 * 2 + 1][1],
                         &Bs[cb][k0 + bFragRow][wn + tn2 * 16 + bFragCol]);
#pragma unroll
            for (int tm = 0; tm < 4; tm++)
#pragma unroll
                for (int tn = 0; tn < 4; tn++)
                    mma16h(acc[tm][tn], a[tm], b[tn]);
        }
        if (kt + 1 < KT)
            asm volatile("cp.async.wait_group 0;" ::: "memory");
        __syncthreads();
    }

#pragma unroll
    for (int tm = 0; tm < 4; tm++) {
        long row0 = bm + wm + tm * 16 + gid;
#pragma unroll
        for (int tn = 0; tn < 4; tn++) {
            int col = bn + wn + tn * 8 + tig * 2;
            if (col < N) {
                float bs0 = bias[col], bs1 = bias[col + 1];
#pragma unroll
                for (int h = 0; h < 2; h++) {
                    long row = row0 + h * 8;
                    float u0 = acc[tm][tn][h * 2 + 0] + bs0;
                    float u1 = acc[tm][tn][h * 2 + 1] + bs1;
                    if (ACT == 1) { u0 = fmaxf(u0, 0.f); u1 = fmaxf(u1, 0.f); }
                    else if (ACT == 2) { u0 = (u0 > 0.f) ? u0 : 0.01f * u0;
                                         u1 = (u1 > 0.f) ? u1 : 0.01f * u1; }
                    else { u0 = tanhf(u0); u1 = tanhf(u1); }
                    if (HOUT) {
                        __half* Cp = (__half*)Call + (long)r * sC;
                        *(__half2*)(Cp + row * ldc + col) = __floats2half2_rn(u0, u1);
                    } else {
                        float* Cp = (float*)Call + (long)r * sC;
                        Cp[row * ldc + col] = u0;
                        Cp[row * ldc + col + 1] = u1;
                    }
                }
            }
        }
    }
}

// ---------------- TF32 tensor GEMM (conv combines) --------------------------
template <int ACT>
__global__ void __launch_bounds__(256, 2)
k_tgemm(const float* __restrict__ Aall, const float* __restrict__ Ball,
        const float* __restrict__ biasAll, float* __restrict__ Call,
        int M, int N, int K, long sA, long sB, long sBias, long sC, int ldc) {
    const int r = blockIdx.z;
    const float* A = Aall + (long)r * sA;
    const float* B = Ball + (long)r * sB;
    const float* bias = biasAll + (long)r * sBias;
    float* C = Call + (long)r * sC;

    __shared__ float As[2][128][20];
    __shared__ float Bs[2][16][136];

    const int t = threadIdx.x;
    const int lane = t & 31;
    const int warp = t >> 5;
    const int wm = (warp >> 2) * 64;
    const int wn = (warp & 3) * 32;
    const long bm = (long)blockIdx.y * 128;
    const int bn = blockIdx.x * 128;

    const int aRow = t >> 2;
    const int aCol = (t & 3) << 2;
    const int bRow = t >> 5;
    const int bCol = (t & 31) << 2;
    const bool bValid = (bn + bCol) < N;
    const int bnc = bValid ? bn + bCol : 0;

    const int gid = lane >> 2;
    const int tig = lane & 3;

    float acc[4][4][4];
#pragma unroll
    for (int i = 0; i < 4; i++)
#pragma unroll
        for (int j = 0; j < 4; j++)
#pragma unroll
            for (int c = 0; c < 4; c++) acc[i][j][c] = 0.f;

    const int KT = K / 16;

    {
        cp16(&As[0][aRow][aCol], A + (bm + aRow) * (long)K + aCol, true);
        cp16(&As[0][aRow + 64][aCol], A + (bm + aRow + 64) * (long)K + aCol, true);
        cp16(&Bs[0][bRow][bCol], B + (long)bRow * N + bnc, bValid);
        cp16(&Bs[0][bRow + 8][bCol], B + (long)(bRow + 8) * N + bnc, bValid);
        asm volatile("cp.async.commit_group;" ::: "memory");
        asm volatile("cp.async.wait_group 0;" ::: "memory");
        __syncthreads();
    }

    for (int kt = 0; kt < KT; kt++) {
        const int cb = kt & 1, nb = (kt + 1) & 1;
        if (kt + 1 < KT) {
            long ko = (long)(kt + 1) * 16;
            cp16(&As[nb][aRow][aCol], A + (bm + aRow) * (long)K + ko + aCol, true);
            cp16(&As[nb][aRow + 64][aCol], A + (bm + aRow + 64) * (long)K + ko + aCol, true);
            cp16(&Bs[nb][bRow][bCol], B + (ko + bRow) * (long)N + bnc, bValid);
            cp16(&Bs[nb][bRow + 8][bCol], B + (ko + bRow + 8) * (long)N + bnc, bValid);
            asm volatile("cp.async.commit_group;" ::: "memory");
        }
#pragma unroll
        for (int k8 = 0; k8 < 2; k8++) {
            const int k0 = k8 * 8;
            unsigned a[4][4], b[4][2];
#pragma unroll
            for (int tm = 0; tm < 4; tm++) {
                int m = wm + tm * 16 + gid;
                a[tm][0] = tf32(As[cb][m][k0 + tig]);
                a[tm][1] = tf32(As[cb][m + 8][k0 + tig]);
                a[tm][2] = tf32(As[cb][m][k0 + tig + 4]);
                a[tm][3] = tf32(As[cb][m + 8][k0 + tig + 4]);
            }
#pragma unroll
            for (int tn = 0; tn < 4; tn++) {
                int n = wn + tn * 8 + gid;
                b[tn][0] = tf32(Bs[cb][k0 + tig][n]);
                b[tn][1] = tf32(Bs[cb][k0 + tig + 4][n]);
            }
#pragma unroll
            for (int tm = 0; tm < 4; tm++)
#pragma unroll
                for (int tn = 0; tn < 4; tn++)
                    mma8(acc[tm][tn], a[tm], b[tn]);
        }
        if (kt + 1 < KT)
            asm volatile("cp.async.wait_group 0;" ::: "memory");
        __syncthreads();
    }

#pragma unroll
    for (int tm = 0; tm < 4; tm++) {
        long row0 = bm + wm + tm * 16 + gid;
#pragma unroll
        for (int tn = 0; tn < 4; tn++) {
            int col = bn + wn + tn * 8 + tig * 2;
            if (col < N) {
                float bs0 = bias[col], bs1 = bias[col + 1];
#pragma unroll
                for (int h = 0; h < 2; h++) {
                    long row = row0 + h * 8;
                    float u0 = acc[tm][tn][h * 2 + 0] + bs0;
                    float u1 = acc[tm][tn][h * 2 + 1] + bs1;
                    if (ACT == 1) { u0 = fmaxf(u0, 0.f); u1 = fmaxf(u1, 0.f); }
                    else if (ACT == 2) { u0 = (u0 > 0.f) ? u0 : 0.01f * u0;
                                         u1 = (u1 > 0.f) ? u1 : 0.01f * u1; }
                    else { u0 = tanhf(u0); u1 = tanhf(u1); }
                    C[row * ldc + col] = u0;
                    C[row * ldc + col + 1] = u1;
                }
            }
        }
    }
}

// pred_missing head
__global__ void k_dw3(const float* __restrict__ z, const float* __restrict__ W,
                      const float* __restrict__ b, float* __restrict__ out) {
    int i = blockIdx.x * blockDim.x + threadIdx.x;
    if (i >= 3 * SSED) return;
    int r = i / SSED;
    int s = i % SSED;
    const float* zz = z + ((long)r * SSED + s) * 32;
    const float* w = W + r * 32;
    float acc = b[r];
#pragma unroll
    for (int k = 0; k < 32; k++) acc = fmaf(zz[k], w[k], acc);
    out[((long)r * SSED + s) * 321] = fmaxf(acc, 0.f);
}

// ---------------- host launch ----------------------------------------------
extern "C" void kernel_launch(void* const* d_in, const int* in_sizes, int n_in,
                              void* d_out, int out_size) {
    static const int MAP_DICT[27] = {0,1,2,3,4,5,6,7,8,9,10,11,12,13,14,15,16,17,18,19,20,21,22,23,24,25,26};
    static const int MAP_SIG[27]  = {0,1,20,21,22,23,24,25,26,2,3,4,5,6,7,8,9,10,11,12,13,14,15,16,17,18,19};
    static const int MAP_ALPHA[27]= {26,21,22,23,12,24,13,25,14,0,3,1,4,2,5,6,9,7,10,8,11,15,18,16,19,17,20};
    const int* MAP = MAP_DICT;
    if (n_in >= 3) {
        if (in_sizes[2] == 12288) MAP = MAP_SIG;
        else if (in_sizes[2] == 4096) MAP = MAP_ALPHA;
    }

    const float* x     = (const float*)d_in[MAP[0]];
    const float* noise = (const float*)d_in[MAP[1]];
    const int* src[3]  = {(const int*)d_in[MAP[3]], (const int*)d_in[MAP[5]], (const int*)d_in[MAP[7]]};
    const int* dst[3]  = {(const int*)d_in[MAP[4]], (const int*)d_in[MAP[6]], (const int*)d_in[MAP[8]]};
    const float* Wc1   = (const float*)d_in[MAP[9]];
    const float* bc1   = (const float*)d_in[MAP[10]];
    const float* Wc2   = (const float*)d_in[MAP[11]];
    const float* bc2   = (const float*)d_in[MAP[12]];
    const float* Wlin  = (const float*)d_in[MAP[13]];
    const float* blin  = (const float*)d_in[MAP[14]];
    const float* dW1   = (const float*)d_in[MAP[15]];
    const float* db1   = (const float*)d_in[MAP[16]];
    const float* dW2   = (const float*)d_in[MAP[17]];
    const float* db2   = (const float*)d_in[MAP[18]];
    const float* dW3   = (const float*)d_in[MAP[19]];
    const float* db3   = (const float*)d_in[MAP[20]];
    const float* fW1   = (const float*)d_in[MAP[21]];
    const float* fb1   = (const float*)d_in[MAP[22]];
    const float* fW2   = (const float*)d_in[MAP[23]];
    const float* fb2   = (const float*)d_in[MAP[24]];
    const float* fW3   = (const float*)d_in[MAP[25]];
    const float* fb3   = (const float*)d_in[MAP[26]];
    float* out = (float*)d_out;

    float *pS, *pH1, *pH2, *pZ2;
    __half *pXh, *pHsh, *pY1h, *pY2h, *pWd1h, *pWd2h, *pWf1h, *pWf2h, *pWf3h;
    cudaGetSymbolAddress((void**)&pS,    g_S);
    cudaGetSymbolAddress((void**)&pH1,   g_h1);
    cudaGetSymbolAddress((void**)&pH2,   g_h2);
    cudaGetSymbolAddress((void**)&pZ2,   g_zd2);
    cudaGetSymbolAddress((void**)&pXh,   g_xh);
    cudaGetSymbolAddress((void**)&pHsh,  g_hsh);
    cudaGetSymbolAddress((void**)&pY1h,  g_y1h);
    cudaGetSymbolAddress((void**)&pY2h,  g_y2h);
    cudaGetSymbolAddress((void**)&pWd1h, g_wd1h);
    cudaGetSymbolAddress((void**)&pWd2h, g_wd2h);
    cudaGetSymbolAddress((void**)&pWf1h, g_wf1h);
    cudaGetSymbolAddress((void**)&pWf2h, g_wf2h);
    cudaGetSymbolAddress((void**)&pWf3h, g_wf3h);

    // ----- fused conversions + degree count (g_cur pre-zeroed) -----
    k_convert<<<(int)((CVT_TOT + 255) / 256), 256>>>(x, dW1, dW2, fW1, fW2, fW3,
                                                     dst[0], dst[1], dst[2]);

    // ----- CSR scan + fill -----
    k_scan<<<3, 1024>>>();
    {
        dim3 g((EE + 255) / 256, 3);
        k_fill<<<g, 256>>>(src[0], dst[0], src[1], dst[1], src[2], dst[2]);
    }

    // ----- conv layer 1 (fp16 gather, MLP=8 via split groups; re-zeroes g_cur) -----
    {
        dim3 g((NN + 15) / 16, 3);
        k_gather_h<<<g, 256>>>(pXh);
    }
    k_tgemm<1><<<dim3(1, NNP / 128, 1), 256>>>(pS, Wc1, bc1, pH1,
                                               NNP, 64, 192, 0, 0, 0, 0, 64);

    // ----- conv layer 2 -----
    {
        dim3 g(SSED / 16, 3);
        k_gather<<<g, 256>>>(pH1, SSED);
    }
    k_tgemm<1><<<dim3(1, SSED / 128, 1), 256>>>(pS, Wc2, bc2, pH2,
                                                SSED, 64, 192, 0, 0, 0, 0, 64);

    // ----- final linear (fp16 hs) -----
    k_final<<<2048, 256>>>(Wlin, blin, noise);

    // ----- decoder: pred_missing -----
    dim3 g1(2, SSED / 128, 3);
    k_hgemm<2, 1><<<g1, 256>>>(pHsh, pWd1h, db1, pY1h, SSED, 256, 64,
                               0, (long)64 * 256, 256, (long)SSED * 256, 256);
    dim3 g2(1, SSED / 128, 3);
    k_hgemm<2, 0><<<g2, 256>>>(pY1h, pWd2h, db2, pZ2, SSED, 32, 256,
                               (long)SSED * 256, (long)256 * 32, 32,
                               (long)SSED * 32, 32);
    k_dw3<<<(3 * SSED + 255) / 256, 256>>>(pZ2, dW3, db3, out);

    // ----- decoder: pred_feat -----
    k_hgemm<1, 1><<<g1, 256>>>(pHsh, pWf1h, fb1, pY1h, SSED, 256, 64,
                               0, (long)64 * 256, 256, (long)SSED * 256, 256);
    dim3 g3(16, SSED / 128, 3);
    k_hgemm<1, 1><<<g3, 256>>>(pY1h, pWf2h, fb2, pY2h, SSED, 2048, 256,
                               (long)SSED * 256, (long)256 * 2048, 2048,
                               (long)SSED * 2048, 2048);
    dim3 g4(3, SSED / 128, 3);
    k_hgemm<3, 0><<<g4, 256>>>(pY2h, pWf3h, fb3, out + 1, SSED, 320, 2048,
                               (long)SSED * 2048, (long)2048 * 320, 320,
                               (long)SSED * 321, 321);
}

// round 14
// speedup vs baseline: 1.0003x; 1.0003x over previous
#include <cuda_runtime.h>
#include <cuda_fp16.h>
#include <math.h>

#define NN 50000
#define NNP 50048
#define EE 800000
#define SSED 8192
#define HD 64

// ---------------- scratch (device globals) ----------------------------------
__device__ int    g_off[3][NN + 1];
__device__ int    g_cur[3 * NN];        // zero-initialized; self-restoring per call
__device__ int    g_esrc[3][EE];
__device__ __half g_xh[NN * HD];
__device__ float  g_S[NNP * 192];
__device__ float  g_h1[NNP * HD];
__device__ float  g_h2[SSED * HD];
__device__ __half g_hsh[SSED * HD];
__device__ float  g_zd2[3 * SSED * 32];
__device__ __half g_y1h[3 * SSED * 256];
__device__ __half g_y2h[3 * SSED * 2048];
__device__ __half g_wd1h[3 * 64 * 256];
__device__ __half g_wd2h[3 * 256 * 32];
__device__ __half g_wf1h[3 * 64 * 256];
__device__ __half g_wf2h[3 * 256 * 2048];
__device__ __half g_wf3h[3 * 2048 * 320];

// ---------------- fused conversion + degree count ----------------------------
#define CVT_XN (NN * HD)
#define CVT_D1 (3 * 64 * 256)
#define CVT_D2 (3 * 256 * 32)
#define CVT_F1 (3 * 64 * 256)
#define CVT_F2 (3 * 256 * 2048)
#define CVT_F3 (3 * 2048 * 320)
#define CVT_TOT ((long)CVT_XN + CVT_D1 + CVT_D2 + CVT_F1 + CVT_F2 + CVT_F3 + 3L * EE)

// g_cur must be zero on entry (static init on call 1; k_gather_h re-zeroes each call)
__global__ void k_convert(const float* __restrict__ x, const float* __restrict__ dW1,
                          const float* __restrict__ dW2, const float* __restrict__ fW1,
                          const float* __restrict__ fW2, const float* __restrict__ fW3,
                          const int* __restrict__ d0, const int* __restrict__ d1,
                          const int* __restrict__ d2) {
    long i = (long)blockIdx.x * blockDim.x + threadIdx.x;
    if (i >= CVT_TOT) return;
    long j = i;
    if (j < CVT_XN) { g_xh[j] = __float2half_rn(x[j]); return; }
    j -= CVT_XN;
    if (j < CVT_D1) { g_wd1h[j] = __float2half_rn(dW1[j]); return; }
    j -= CVT_D1;
    if (j < CVT_D2) { g_wd2h[j] = __float2half_rn(dW2[j]); return; }
    j -= CVT_D2;
    if (j < CVT_F1) { g_wf1h[j] = __float2half_rn(fW1[j]); return; }
    j -= CVT_F1;
    if (j < CVT_F2) { g_wf2h[j] = __float2half_rn(fW2[j]); return; }
    j -= CVT_F2;
    if (j < CVT_F3) { g_wf3h[j] = __float2half_rn(fW3[j]); return; }
    j -= CVT_F3;
    // degree counting
    int r = (int)(j / EE);
    int e = (int)(j % EE);
    const int* d = (r == 0) ? d0 : ((r == 1) ? d1 : d2);
    atomicAdd(&g_cur[r * NN + d[e]], 1);
}

// ---------------- CSR scan + fill --------------------------------------------
__global__ void k_scan() {
    const int r = blockIdx.x;
    const int tid = threadIdx.x;
    __shared__ int sm[1024];
    const int CH = 49;
    int t0 = tid * CH;
    int t1 = t0 + CH; if (t1 > NN) t1 = NN;
    int sum = 0;
    for (int i = t0; i < t1; i++) sum += g_cur[r * NN + i];
    sm[tid] = sum;
    __syncthreads();
#pragma unroll
    for (int o = 1; o < 1024; o <<= 1) {
        int v = (tid >= o) ? sm[tid - o] : 0;
        __syncthreads();
        sm[tid] += v;
        __syncthreads();
    }
    int run = sm[tid] - sum;
    for (int i = t0; i < t1; i++) {
        int c = g_cur[r * NN + i];
        g_off[r][i] = run;
        run += c;
        g_cur[r * NN + i] = 0;          // reset for fill cursors
    }
    if (tid == 1023) g_off[r][NN] = run;
}

__global__ void k_fill(const int* __restrict__ s0, const int* __restrict__ d0,
                       const int* __restrict__ s1, const int* __restrict__ d1,
                       const int* __restrict__ s2, const int* __restrict__ d2) {
    const int r = blockIdx.y;
    const int* s = (r == 0) ? s0 : ((r == 1) ? s1 : s2);
    const int* d = (r == 0) ? d0 : ((r == 1) ? d1 : d2);
    int e = blockIdx.x * blockDim.x + threadIdx.x;
    if (e < EE) {
        int dv = d[e];
        int pos = g_off[r][dv] + atomicAdd(&g_cur[r * NN + dv], 1);
        g_esrc[r][pos] = s[e];
    }
}

// ---------------- gathers ----------------------------------------------------
__device__ __forceinline__ void addh8(float* a, uint4 v) {
    const __half2* hv = (const __half2*)&v;
#pragma unroll
    for (int k = 0; k < 4; k++) {
        float2 f = __half22float2(hv[k]);
        a[2 * k] += f.x;
        a[2 * k + 1] += f.y;
    }
}

// layer-1 gather fp16: 16 thr/node = two 8-lane groups splitting the edge list.
// Also re-zeroes g_cur (post-fill) so next call's k_convert counts from zero.
__global__ void k_gather_h(const __half* __restrict__ h) {
    const int r = blockIdx.y;
    const int t = threadIdx.x;
    int node = blockIdx.x * 16 + (t >> 4);
    if (node >= NN) return;
    if ((t & 15) == 0) g_cur[r * NN + node] = 0;
    const int sub = (t >> 3) & 1;
    const int q = (t & 7) << 3;
    const int b = g_off[r][node], e2 = g_off[r][node + 1];
    const int cnt = e2 - b;
    const int half = (cnt + 1) >> 1;
    const int gb = b + sub * half;
    const int ge = sub ? e2 : b + half;
    const int* es = g_esrc[r];
    float a0[8] = {0,0,0,0,0,0,0,0}, a1[8] = {0,0,0,0,0,0,0,0};
    float a2[8] = {0,0,0,0,0,0,0,0}, a3[8] = {0,0,0,0,0,0,0,0};
    int i = gb;
    for (; i + 4 <= ge; i += 4) {
        int s0 = __ldg(es + i), s1 = __ldg(es + i + 1);
        int s2 = __ldg(es + i + 2), s3 = __ldg(es + i + 3);
        uint4 v0 = *(const uint4*)(h + (long)s0 * HD + q);
        uint4 v1 = *(const uint4*)(h + (long)s1 * HD + q);
        uint4 v2 = *(const uint4*)(h + (long)s2 * HD + q);
        uint4 v3 = *(const uint4*)(h + (long)s3 * HD + q);
        addh8(a0, v0); addh8(a1, v1); addh8(a2, v2); addh8(a3, v3);
    }
    for (; i < ge; i++) {
        uint4 v = *(const uint4*)(h + (long)__ldg(es + i) * HD + q);
        addh8(a0, v);
    }
    float inv = (cnt > 0) ? 1.f / (float)cnt : 1.f;
#pragma unroll
    for (int k = 0; k < 8; k++) {
        float v = a0[k] + a1[k] + a2[k] + a3[k];
        v += __shfl_xor_sync(0xffffffffu, v, 8);
        a0[k] = v * inv;
    }
    if (sub == 0) {
        float* dst = g_S + (long)node * 192 + r * HD + q;
        *(float4*)dst = make_float4(a0[0], a0[1], a0[2], a0[3]);
        *(float4*)(dst + 4) = make_float4(a0[4], a0[5], a0[6], a0[7]);
    }
}

// layer-2 gather from fp32 h1: 16 thr per node, MLP=4
__global__ void k_gather(const float* __restrict__ h, int nLimit) {
    const int r = blockIdx.y;
    int node = blockIdx.x * 16 + (threadIdx.x >> 4);
    if (node >= nLimit) return;
    const int q = (threadIdx.x & 15) << 2;
    const int b = g_off[r][node], e2 = g_off[r][node + 1];
    const int* es = g_esrc[r];
    float4 a0 = make_float4(0.f, 0.f, 0.f, 0.f);
    float4 a1 = a0, a2 = a0, a3 = a0;
    int i = b;
    for (; i + 4 <= e2; i += 4) {
        int s0 = __ldg(es + i), s1 = __ldg(es + i + 1);
        int s2 = __ldg(es + i + 2), s3 = __ldg(es + i + 3);
        float4 v0 = *(const float4*)(h + (long)s0 * HD + q);
        float4 v1 = *(const float4*)(h + (long)s1 * HD + q);
        float4 v2 = *(const float4*)(h + (long)s2 * HD + q);
        float4 v3 = *(const float4*)(h + (long)s3 * HD + q);
        a0.x += v0.x; a0.y += v0.y; a0.z += v0.z; a0.w += v0.w;
        a1.x += v1.x; a1.y += v1.y; a1.z += v1.z; a1.w += v1.w;
        a2.x += v2.x; a2.y += v2.y; a2.z += v2.z; a2.w += v2.w;
        a3.x += v3.x; a3.y += v3.y; a3.z += v3.z; a3.w += v3.w;
    }
    for (; i < e2; i++) {
        float4 v = *(const float4*)(h + (long)__ldg(es + i) * HD + q);
        a0.x += v.x; a0.y += v.y; a0.z += v.z; a0.w += v.w;
    }
    a0.x += a1.x + a2.x + a3.x;
    a0.y += a1.y + a2.y + a3.y;
    a0.z += a1.z + a2.z + a3.z;
    a0.w += a1.w + a2.w + a3.w;
    float inv = (e2 > b) ? 1.f / (float)(e2 - b) : 1.f;
    a0.x *= inv; a0.y *= inv; a0.z *= inv; a0.w *= inv;
    *(float4*)(g_S + (long)node * 192 + r * HD + q) = a0;
}

__global__ void k_final(const float* __restrict__ W, const float* __restrict__ bias,
                        const float* __restrict__ noise) {
    __shared__ float sW[HD * HD];
    __shared__ float sS[4 * HD];
    for (int i = threadIdx.x; i < HD * HD; i += blockDim.x) sW[i] = W[i];
    __syncthreads();
    const int j = threadIdx.x & 63;
    const int ln = threadIdx.x >> 6;
    for (int n0 = blockIdx.x * 4; n0 < SSED; n0 += gridDim.x * 4) {
        int n = n0 + ln;
        sS[ln * HD + j] = g_h2[(long)n * HD + j];
        __syncthreads();
        float acc = bias[j];
#pragma unroll
        for (int k = 0; k < HD; k++)
            acc = fmaf(sS[ln * HD + k], sW[k * HD + j], acc);
        float v = (acc > 0.f) ? acc : 0.01f * acc;
        g_hsh[(long)n * HD + j] = __float2half_rn(v + noise[(long)n * HD + j]);
        __syncthreads();
    }
}

// ---------------- common asm helpers ----------------------------------------
__device__ __forceinline__ void cp16(void* smem, const void* gmem, bool valid) {
    unsigned s = (unsigned)__cvta_generic_to_shared(smem);
    int sz = valid ? 16 : 0;
    asm volatile("cp.async.cg.shared.global [%0], [%1], 16, %2;"
                 :: "r"(s), "l"(gmem), "r"(sz) : "memory");
}
__device__ __forceinline__ unsigned tf32(float f) {
    unsigned u;
    asm("cvt.rna.tf32.f32 %0, %1;" : "=r"(u) : "f"(f));
    return u;
}
__device__ __forceinline__ void mma8(float* c, const unsigned* a, const unsigned* b) {
    asm volatile("mma.sync.aligned.m16n8k8.row.col.f32.tf32.tf32.f32 "
                 "{%0,%1,%2,%3}, {%4,%5,%6,%7}, {%8,%9}, {%0,%1,%2,%3};"
                 : "+f"(c[0]), "+f"(c[1]), "+f"(c[2]), "+f"(c[3])
                 : "r"(a[0]), "r"(a[1]), "r"(a[2]), "r"(a[3]), "r"(b[0]), "r"(b[1]));
}
__device__ __forceinline__ void mma16h(float* c, const unsigned* a, const unsigned* b) {
    asm volatile("mma.sync.aligned.m16n8k16.row.col.f32.f16.f16.f32 "
                 "{%0,%1,%2,%3}, {%4,%5,%6,%7}, {%8,%9}, {%0,%1,%2,%3};"
                 : "+f"(c[0]), "+f"(c[1]), "+f"(c[2]), "+f"(c[3])
                 : "r"(a[0]), "r"(a[1]), "r"(a[2]), "r"(a[3]), "r"(b[0]), "r"(b[1]));
}
__device__ __forceinline__ void ldsm_x4(unsigned& r0, unsigned& r1, unsigned& r2,
                                        unsigned& r3, const void* p) {
    unsigned a = (unsigned)__cvta_generic_to_shared(p);
    asm volatile("ldmatrix.sync.aligned.m8n8.x4.shared.b16 {%0,%1,%2,%3}, [%4];"
                 : "=r"(r0), "=r"(r1), "=r"(r2), "=r"(r3) : "r"(a));
}
__device__ __forceinline__ void ldsm_x4t(unsigned& r0, unsigned& r1, unsigned& r2,
                                         unsigned& r3, const void* p) {
    unsigned a = (unsigned)__cvta_generic_to_shared(p);
    asm volatile("ldmatrix.sync.aligned.m8n8.x4.trans.shared.b16 {%0,%1,%2,%3}, [%4];"
                 : "=r"(r0), "=r"(r1), "=r"(r2), "=r"(r3) : "r"(a));
}

// ---------------- fp16 tensor-core GEMM (128x128 CTA, 64x32 warp, BK=32) ----
template <int ACT, int HOUT>
__global__ void __launch_bounds__(256, 2)
k_hgemm(const __half* __restrict__ Aall, const __half* __restrict__ Ball,
        const float* __restrict__ biasAll, void* __restrict__ Call,
        int M, int N, int K, long sA, long sB, long sBias, long sC, int ldc) {
    const int r = blockIdx.z;
    const __half* A = Aall + (long)r * sA;
    const __half* B = Ball + (long)r * sB;
    const float* bias = biasAll + (long)r * sBias;

    __shared__ __half As[2][128][40];
    __shared__ __half Bs[2][32][136];

    const int t = threadIdx.x;
    const int lane = t & 31;
    const int warp = t >> 5;
    const int wm = (warp >> 2) * 64;
    const int wn = (warp & 3) * 32;
    const long bm = (long)blockIdx.y * 128;
    const int bn = blockIdx.x * 128;

    const int aRow = t >> 1;
    const int aCol = (t & 1) << 4;
    const int bRow = t >> 3;
    const int bCol = (t & 7) << 4;
    const bool bv0 = (bn + bCol) < N;
    const bool bv1 = (bn + bCol + 8) < N;
    const int bc0 = bv0 ? bn + bCol : 0;
    const int bc1 = bv1 ? bn + bCol + 8 : 0;

    const int gid = lane >> 2;
    const int tig = lane & 3;

    float acc[4][4][4];
#pragma unroll
    for (int i = 0; i < 4; i++)
#pragma unroll
        for (int j = 0; j < 4; j++)
#pragma unroll
            for (int c = 0; c < 4; c++) acc[i][j][c] = 0.f;

    const int KT = K / 32;

    {
        cp16(&As[0][aRow][aCol], A + (bm + aRow) * (long)K + aCol, true);
        cp16(&As[0][aRow][aCol + 8], A + (bm + aRow) * (long)K + aCol + 8, true);
        cp16(&Bs[0][bRow][bCol], B + (long)bRow * N + bc0, bv0);
        cp16(&Bs[0][bRow][bCol + 8], B + (long)bRow * N + bc1, bv1);
        asm volatile("cp.async.commit_group;" ::: "memory");
        asm volatile("cp.async.wait_group 0;" ::: "memory");
        __syncthreads();
    }

    const int aFragRow = lane & 15;
    const int aFragCol = (lane >> 4) << 3;
    const int bFragRow = lane & 15;
    const int bFragCol = (lane >> 4) << 3;

    for (int kt = 0; kt < KT; kt++) {
        const int cb = kt & 1, nb = (kt + 1) & 1;
        if (kt + 1 < KT) {
            long ko = (long)(kt + 1) * 32;
            cp16(&As[nb][aRow][aCol], A + (bm + aRow) * (long)K + ko + aCol, true);
            cp16(&As[nb][aRow][aCol + 8], A + (bm + aRow) * (long)K + ko + aCol + 8, true);
            cp16(&Bs[nb][bRow][bCol], B + (ko + bRow) * (long)N + bc0, bv0);
            cp16(&Bs[nb][bRow][bCol + 8], B + (ko + bRow) * (long)N + bc1, bv1);
            asm volatile("cp.async.commit_group;" ::: "memory");
        }
#pragma unroll
        for (int kk = 0; kk < 2; kk++) {
            const int k0 = kk * 16;
            unsigned a[4][4], b[4][2];
#pragma unroll
            for (int tm = 0; tm < 4; tm++)
                ldsm_x4(a[tm][0], a[tm][1], a[tm][2], a[tm][3],
                        &As[cb][wm + tm * 16 + aFragRow][k0 + aFragCol]);
#pragma unroll
            for (int tn2 = 0; tn2 < 2; tn2++)
                ldsm_x4t(b[tn2 * 2][0], b[tn2 * 2][1], b[tn2 * 2 + 1][0], b[tn2 * 2 + 1][1],
                         &Bs[cb][k0 + bFragRow][wn + tn2 * 16 + bFragCol]);
#pragma unroll
            for (int tm = 0; tm < 4; tm++)
#pragma unroll
                for (int tn = 0; tn < 4; tn++)
                    mma16h(acc[tm][tn], a[tm], b[tn]);
        }
        if (kt + 1 < KT)
            asm volatile("cp.async.wait_group 0;" ::: "memory");
        __syncthreads();
    }

#pragma unroll
    for (int tm = 0; tm < 4; tm++) {
        long row0 = bm + wm + tm * 16 + gid;
#pragma unroll
        for (int tn = 0; tn < 4; tn++) {
            int col = bn + wn + tn * 8 + tig * 2;
            if (col < N) {
                float bs0 = bias[col], bs1 = bias[col + 1];
#pragma unroll
                for (int h = 0; h < 2; h++) {
                    long row = row0 + h * 8;
                    float u0 = acc[tm][tn][h * 2 + 0] + bs0;
                    float u1 = acc[tm][tn][h * 2 + 1] + bs1;
                    if (ACT == 1) { u0 = fmaxf(u0, 0.f); u1 = fmaxf(u1, 0.f); }
                    else if (ACT == 2) { u0 = (u0 > 0.f) ? u0 : 0.01f * u0;
                                         u1 = (u1 > 0.f) ? u1 : 0.01f * u1; }
                    else { u0 = tanhf(u0); u1 = tanhf(u1); }
                    if (HOUT) {
                        __half* Cp = (__half*)Call + (long)r * sC;
                        *(__half2*)(Cp + row * ldc + col) = __floats2half2_rn(u0, u1);
                    } else {
                        float* Cp = (float*)Call + (long)r * sC;
                        Cp[row * ldc + col] = u0;
                        Cp[row * ldc + col + 1] = u1;
                    }
                }
            }
        }
    }
}

// ---------------- TF32 tensor GEMM (conv combines) --------------------------
template <int ACT>
__global__ void __launch_bounds__(256, 2)
k_tgemm(const float* __restrict__ Aall, const float* __restrict__ Ball,
        const float* __restrict__ biasAll, float* __restrict__ Call,
        int M, int N, int K, long sA, long sB, long sBias, long sC, int ldc) {
    const int r = blockIdx.z;
    const float* A = Aall + (long)r * sA;
    const float* B = Ball + (long)r * sB;
    const float* bias = biasAll + (long)r * sBias;
    float* C = Call + (long)r * sC;

    __shared__ float As[2][128][20];
    __shared__ float Bs[2][16][136];

    const int t = threadIdx.x;
    const int lane = t & 31;
    const int warp = t >> 5;
    const int wm = (warp >> 2) * 64;
    const int wn = (warp & 3) * 32;
    const long bm = (long)blockIdx.y * 128;
    const int bn = blockIdx.x * 128;

    const int aRow = t >> 2;
    const int aCol = (t & 3) << 2;
    const int bRow = t >> 5;
    const int bCol = (t & 31) << 2;
    const bool bValid = (bn + bCol) < N;
    const int bnc = bValid ? bn + bCol : 0;

    const int gid = lane >> 2;
    const int tig = lane & 3;

    float acc[4][4][4];
#pragma unroll
    for (int i = 0; i < 4; i++)
#pragma unroll
        for (int j = 0; j < 4; j++)
#pragma unroll
            for (int c = 0; c < 4; c++) acc[i][j][c] = 0.f;

    const int KT = K / 16;

    {
        cp16(&As[0][aRow][aCol], A + (bm + aRow) * (long)K + aCol, true);
        cp16(&As[0][aRow + 64][aCol], A + (bm + aRow + 64) * (long)K + aCol, true);
        cp16(&Bs[0][bRow][bCol], B + (long)bRow * N + bnc, bValid);
        cp16(&Bs[0][bRow + 8][bCol], B + (long)(bRow + 8) * N + bnc, bValid);
        asm volatile("cp.async.commit_group;" ::: "memory");
        asm volatile("cp.async.wait_group 0;" ::: "memory");
        __syncthreads();
    }

    for (int kt = 0; kt < KT; kt++) {
        const int cb = kt & 1, nb = (kt + 1) & 1;
        if (kt + 1 < KT) {
            long ko = (long)(kt + 1) * 16;
            cp16(&As[nb][aRow][aCol], A + (bm + aRow) * (long)K + ko + aCol, true);
            cp16(&As[nb][aRow + 64][aCol], A + (bm + aRow + 64) * (long)K + ko + aCol, true);
            cp16(&Bs[nb][bRow][bCol], B + (ko + bRow) * (long)N + bnc, bValid);
            cp16(&Bs[nb][bRow + 8][bCol], B + (ko + bRow + 8) * (long)N + bnc, bValid);
            asm volatile("cp.async.commit_group;" ::: "memory");
        }
#pragma unroll
        for (int k8 = 0; k8 < 2; k8++) {
            const int k0 = k8 * 8;
            unsigned a[4][4], b[4][2];
#pragma unroll
            for (int tm = 0; tm < 4; tm++) {
                int m = wm + tm * 16 + gid;
                a[tm][0] = tf32(As[cb][m][k0 + tig]);
                a[tm][1] = tf32(As[cb][m + 8][k0 + tig]);
                a[tm][2] = tf32(As[cb][m][k0 + tig + 4]);
                a[tm][3] = tf32(As[cb][m + 8][k0 + tig + 4]);
            }
#pragma unroll
            for (int tn = 0; tn < 4; tn++) {
                int n = wn + tn * 8 + gid;
                b[tn][0] = tf32(Bs[cb][k0 + tig][n]);
                b[tn][1] = tf32(Bs[cb][k0 + tig + 4][n]);
            }
#pragma unroll
            for (int tm = 0; tm < 4; tm++)
#pragma unroll
                for (int tn = 0; tn < 4; tn++)
                    mma8(acc[tm][tn], a[tm], b[tn]);
        }
        if (kt + 1 < KT)
            asm volatile("cp.async.wait_group 0;" ::: "memory");
        __syncthreads();
    }

#pragma unroll
    for (int tm = 0; tm < 4; tm++) {
        long row0 = bm + wm + tm * 16 + gid;
#pragma unroll
        for (int tn = 0; tn < 4; tn++) {
            int col = bn + wn + tn * 8 + tig * 2;
            if (col < N) {
                float bs0 = bias[col], bs1 = bias[col + 1];
#pragma unroll
                for (int h = 0; h < 2; h++) {
                    long row = row0 + h * 8;
                    float u0 = acc[tm][tn][h * 2 + 0] + bs0;
                    float u1 = acc[tm][tn][h * 2 + 1] + bs1;
                    if (ACT == 1) { u0 = fmaxf(u0, 0.f); u1 = fmaxf(u1, 0.f); }
                    else if (ACT == 2) { u0 = (u0 > 0.f) ? u0 : 0.01f * u0;
                                         u1 = (u1 > 0.f) ? u1 : 0.01f * u1; }
                    else { u0 = tanhf(u0); u1 = tanhf(u1); }
                    C[row * ldc + col] = u0;
                    C[row * ldc + col + 1] = u1;
                }
            }
        }
    }
}

// pred_missing head
__global__ void k_dw3(const float* __restrict__ z, const float* __restrict__ W,
                      const float* __restrict__ b, float* __restrict__ out) {
    int i = blockIdx.x * blockDim.x + threadIdx.x;
    if (i >= 3 * SSED) return;
    int r = i / SSED;
    int s = i % SSED;
    const float* zz = z + ((long)r * SSED + s) * 32;
    const float* w = W + r * 32;
    float acc = b[r];
#pragma unroll
    for (int k = 0; k < 32; k++) acc = fmaf(zz[k], w[k], acc);
    out[((long)r * SSED + s) * 321] = fmaxf(acc, 0.f);
}

// ---------------- host launch ----------------------------------------------
extern "C" void kernel_launch(void* const* d_in, const int* in_sizes, int n_in,
                              void* d_out, int out_size) {
    static const int MAP_DICT[27] = {0,1,2,3,4,5,6,7,8,9,10,11,12,13,14,15,16,17,18,19,20,21,22,23,24,25,26};
    static const int MAP_SIG[27]  = {0,1,20,21,22,23,24,25,26,2,3,4,5,6,7,8,9,10,11,12,13,14,15,16,17,18,19};
    static const int MAP_ALPHA[27]= {26,21,22,23,12,24,13,25,14,0,3,1,4,2,5,6,9,7,10,8,11,15,18,16,19,17,20};
    const int* MAP = MAP_DICT;
    if (n_in >= 3) {
        if (in_sizes[2] == 12288) MAP = MAP_SIG;
        else if (in_sizes[2] == 4096) MAP = MAP_ALPHA;
    }

    const float* x     = (const float*)d_in[MAP[0]];
    const float* noise = (const float*)d_in[MAP[1]];
    const int* src[3]  = {(const int*)d_in[MAP[3]], (const int*)d_in[MAP[5]], (const int*)d_in[MAP[7]]};
    const int* dst[3]  = {(const int*)d_in[MAP[4]], (const int*)d_in[MAP[6]], (const int*)d_in[MAP[8]]};
    const float* Wc1   = (const float*)d_in[MAP[9]];
    const float* bc1   = (const float*)d_in[MAP[10]];
    const float* Wc2   = (const float*)d_in[MAP[11]];
    const float* bc2   = (const float*)d_in[MAP[12]];
    const float* Wlin  = (const float*)d_in[MAP[13]];
    const float* blin  = (const float*)d_in[MAP[14]];
    const float* dW1   = (const float*)d_in[MAP[15]];
    const float* db1   = (const float*)d_in[MAP[16]];
    const float* dW2   = (const float*)d_in[MAP[17]];
    const float* db2   = (const float*)d_in[MAP[18]];
    const float* dW3   = (const float*)d_in[MAP[19]];
    const float* db3   = (const float*)d_in[MAP[20]];
    const float* fW1   = (const float*)d_in[MAP[21]];
    const float* fb1   = (const float*)d_in[MAP[22]];
    const float* fW2   = (const float*)d_in[MAP[23]];
    const float* fb2   = (const float*)d_in[MAP[24]];
    const float* fW3   = (const float*)d_in[MAP[25]];
    const float* fb3   = (const float*)d_in[MAP[26]];
    float* out = (float*)d_out;

    float *pS, *pH1, *pH2, *pZ2;
    __half *pXh, *pHsh, *pY1h, *pY2h, *pWd1h, *pWd2h, *pWf1h, *pWf2h, *pWf3h;
    cudaGetSymbolAddress((void**)&pS,    g_S);
    cudaGetSymbolAddress((void**)&pH1,   g_h1);
    cudaGetSymbolAddress((void**)&pH2,   g_h2);
    cudaGetSymbolAddress((void**)&pZ2,   g_zd2);
    cudaGetSymbolAddress((void**)&pXh,   g_xh);
    cudaGetSymbolAddress((void**)&pHsh,  g_hsh);
    cudaGetSymbolAddress((void**)&pY1h,  g_y1h);
    cudaGetSymbolAddress((void**)&pY2h,  g_y2h);
    cudaGetSymbolAddress((void**)&pWd1h, g_wd1h);
    cudaGetSymbolAddress((void**)&pWd2h, g_wd2h);
    cudaGetSymbolAddress((void**)&pWf1h, g_wf1h);
    cudaGetSymbolAddress((void**)&pWf2h, g_wf2h);
    cudaGetSymbolAddress((void**)&pWf3h, g_wf3h);

    // ----- fused conversions + degree count (g_cur pre-zeroed) -----
    k_convert<<<(int)((CVT_TOT + 255) / 256), 256>>>(x, dW1, dW2, fW1, fW2, fW3,
                                                     dst[0], dst[1], dst[2]);

    // ----- CSR scan + fill -----
    k_scan<<<3, 1024>>>();
    {
        dim3 g((EE + 255) / 256, 3);
        k_fill<<<g, 256>>>(src[0], dst[0], src[1], dst[1], src[2], dst[2]);
    }

    // ----- conv layer 1 (fp16 gather, MLP=8 via split groups; re-zeroes g_cur) -----
    {
        dim3 g((NN + 15) / 16, 3);
        k_gather_h<<<g, 256>>>(pXh);
    }
    k_tgemm<1><<<dim3(1, NNP / 128, 1), 256>>>(pS, Wc1, bc1, pH1,
                                               NNP, 64, 192, 0, 0, 0, 0, 64);

    // ----- conv layer 2 -----
    {
        dim3 g(SSED / 16, 3);
        k_gather<<<g, 256>>>(pH1, SSED);
    }
    k_tgemm<1><<<dim3(1, SSED / 128, 1), 256>>>(pS, Wc2, bc2, pH2,
                                                SSED, 64, 192, 0, 0, 0, 0, 64);

    // ----- final linear (fp16 hs) -----
    k_final<<<2048, 256>>>(Wlin, blin, noise);

    // ----- decoder: pred_missing -----
    dim3 g1(2, SSED / 128, 3);
    k_hgemm<2, 1><<<g1, 256>>>(pHsh, pWd1h, db1, pY1h, SSED, 256, 64,
                               0, (long)64 * 256, 256, (long)SSED * 256, 256);
    dim3 g2(1, SSED / 128, 3);
    k_hgemm<2, 0><<<g2, 256>>>(pY1h, pWd2h, db2, pZ2, SSED, 32, 256,
                               (long)SSED * 256, (long)256 * 32, 32,
                               (long)SSED * 32, 32);
    k_dw3<<<(3 * SSED + 255) / 256, 256>>>(pZ2, dW3, db3, out);

    // ----- decoder: pred_feat -----
    k_hgemm<1, 1><<<g1, 256>>>(pHsh, pWf1h, fb1, pY1h, SSED, 256, 64,
                               0, (long)64 * 256, 256, (long)SSED * 256, 256);
    dim3 g3(16, SSED / 128, 3);
    k_hgemm<1, 1><<<g3, 256>>>(pY1h, pWf2h, fb2, pY2h, SSED, 2048, 256,
                               (long)SSED * 256, (long)256 * 2048, 2048,
                               (long)SSED * 2048, 2048);
    dim3 g4(3, SSED / 128, 3);
    k_hgemm<3, 0><<<g4, 256>>>(pY2h, pWf3h, fb3, out + 1, SSED, 320, 2048,
                               (long)SSED * 2048, (long)2048 * 320, 320,
                               (long)SSED * 321, 321);
}

// round 15
// speedup vs baseline: 1.0043x; 1.0040x over previous
#include <cuda_runtime.h>
#include <cuda_fp16.h>
#include <math.h>

#define NN 50000
#define NNP 50048
#define EE 800000
#define SSED 8192
#define HD 64

// ---------------- scratch (device globals) ----------------------------------
__device__ int    g_off[3][NN + 1];
__device__ int    g_cur[3 * NN];        // zero-initialized; self-restoring per call
__device__ int    g_esrc[3][EE];
__device__ __half g_xh[NN * HD];
__device__ float  g_S[NNP * 192];
__device__ float  g_h1[NNP * HD];
__device__ float  g_h2[SSED * HD];
__device__ __half g_hsh[SSED * HD];
__device__ float  g_zd2[3 * SSED * 32];
__device__ __half g_y1h[3 * SSED * 256];
__device__ __half g_y2h[3 * SSED * 2048];
__device__ __half g_wd1h[3 * 64 * 256];
__device__ __half g_wd2h[3 * 256 * 32];
__device__ __half g_wf1h[3 * 64 * 256];
__device__ __half g_wf2h[3 * 256 * 2048];
__device__ __half g_wf3h[3 * 2048 * 320];

// ---------------- fused conversion + degree count ----------------------------
#define CVT_XN (NN * HD)
#define CVT_D1 (3 * 64 * 256)
#define CVT_D2 (3 * 256 * 32)
#define CVT_F1 (3 * 64 * 256)
#define CVT_F2 (3 * 256 * 2048)
#define CVT_F3 (3 * 2048 * 320)
#define CVT_TOT ((long)CVT_XN + CVT_D1 + CVT_D2 + CVT_F1 + CVT_F2 + CVT_F3 + 3L * EE)

// g_cur must be zero on entry (static init on call 1; k_gather_h re-zeroes each call)
__global__ void k_convert(const float* __restrict__ x, const float* __restrict__ dW1,
                          const float* __restrict__ dW2, const float* __restrict__ fW1,
                          const float* __restrict__ fW2, const float* __restrict__ fW3,
                          const int* __restrict__ d0, const int* __restrict__ d1,
                          const int* __restrict__ d2) {
    long i = (long)blockIdx.x * blockDim.x + threadIdx.x;
    if (i >= CVT_TOT) return;
    long j = i;
    if (j < CVT_XN) { g_xh[j] = __float2half_rn(x[j]); return; }
    j -= CVT_XN;
    if (j < CVT_D1) { g_wd1h[j] = __float2half_rn(dW1[j]); return; }
    j -= CVT_D1;
    if (j < CVT_D2) { g_wd2h[j] = __float2half_rn(dW2[j]); return; }
    j -= CVT_D2;
    if (j < CVT_F1) { g_wf1h[j] = __float2half_rn(fW1[j]); return; }
    j -= CVT_F1;
    if (j < CVT_F2) { g_wf2h[j] = __float2half_rn(fW2[j]); return; }
    j -= CVT_F2;
    if (j < CVT_F3) { g_wf3h[j] = __float2half_rn(fW3[j]); return; }
    j -= CVT_F3;
    // degree counting
    int r = (int)(j / EE);
    int e = (int)(j % EE);
    const int* d = (r == 0) ? d0 : ((r == 1) ? d1 : d2);
    atomicAdd(&g_cur[r * NN + d[e]], 1);
}

// ---------------- CSR scan + fill --------------------------------------------
__global__ void k_scan() {
    const int r = blockIdx.x;
    const int tid = threadIdx.x;
    __shared__ int sm[1024];
    const int CH = 49;
    int t0 = tid * CH;
    int t1 = t0 + CH; if (t1 > NN) t1 = NN;
    int sum = 0;
    for (int i = t0; i < t1; i++) sum += g_cur[r * NN + i];
    sm[tid] = sum;
    __syncthreads();
#pragma unroll
    for (int o = 1; o < 1024; o <<= 1) {
        int v = (tid >= o) ? sm[tid - o] : 0;
        __syncthreads();
        sm[tid] += v;
        __syncthreads();
    }
    int run = sm[tid] - sum;
    for (int i = t0; i < t1; i++) {
        int c = g_cur[r * NN + i];
        g_off[r][i] = run;
        run += c;
        g_cur[r * NN + i] = 0;          // reset for fill cursors
    }
    if (tid == 1023) g_off[r][NN] = run;
}

__global__ void k_fill(const int* __restrict__ s0, const int* __restrict__ d0,
                       const int* __restrict__ s1, const int* __restrict__ d1,
                       const int* __restrict__ s2, const int* __restrict__ d2) {
    const int r = blockIdx.y;
    const int* s = (r == 0) ? s0 : ((r == 1) ? s1 : s2);
    const int* d = (r == 0) ? d0 : ((r == 1) ? d1 : d2);
    int e = blockIdx.x * blockDim.x + threadIdx.x;
    if (e < EE) {
        int dv = d[e];
        int pos = g_off[r][dv] + atomicAdd(&g_cur[r * NN + dv], 1);
        g_esrc[r][pos] = s[e];
    }
}

// ---------------- gathers ----------------------------------------------------
__device__ __forceinline__ void addh8(float* a, uint4 v) {
    const __half2* hv = (const __half2*)&v;
#pragma unroll
    for (int k = 0; k < 4; k++) {
        float2 f = __half22float2(hv[k]);
        a[2 * k] += f.x;
        a[2 * k + 1] += f.y;
    }
}

// layer-1 gather fp16: 16 thr/node = two 8-lane groups splitting the edge list.
// Also re-zeroes g_cur (post-fill) so next call's k_convert counts from zero.
__global__ void k_gather_h(const __half* __restrict__ h) {
    const int r = blockIdx.y;
    const int t = threadIdx.x;
    int node = blockIdx.x * 16 + (t >> 4);
    if (node >= NN) return;
    if ((t & 15) == 0) g_cur[r * NN + node] = 0;
    const int sub = (t >> 3) & 1;
    const int q = (t & 7) << 3;
    const int b = g_off[r][node], e2 = g_off[r][node + 1];
    const int cnt = e2 - b;
    const int half = (cnt + 1) >> 1;
    const int gb = b + sub * half;
    const int ge = sub ? e2 : b + half;
    const int* es = g_esrc[r];
    float a0[8] = {0,0,0,0,0,0,0,0}, a1[8] = {0,0,0,0,0,0,0,0};
    float a2[8] = {0,0,0,0,0,0,0,0}, a3[8] = {0,0,0,0,0,0,0,0};
    int i = gb;
    for (; i + 4 <= ge; i += 4) {
        int s0 = __ldg(es + i), s1 = __ldg(es + i + 1);
        int s2 = __ldg(es + i + 2), s3 = __ldg(es + i + 3);
        uint4 v0 = *(const uint4*)(h + (long)s0 * HD + q);
        uint4 v1 = *(const uint4*)(h + (long)s1 * HD + q);
        uint4 v2 = *(const uint4*)(h + (long)s2 * HD + q);
        uint4 v3 = *(const uint4*)(h + (long)s3 * HD + q);
        addh8(a0, v0); addh8(a1, v1); addh8(a2, v2); addh8(a3, v3);
    }
    for (; i < ge; i++) {
        uint4 v = *(const uint4*)(h + (long)__ldg(es + i) * HD + q);
        addh8(a0, v);
    }
    float inv = (cnt > 0) ? 1.f / (float)cnt : 1.f;
#pragma unroll
    for (int k = 0; k < 8; k++) {
        float v = a0[k] + a1[k] + a2[k] + a3[k];
        v += __shfl_xor_sync(0xffffffffu, v, 8);
        a0[k] = v * inv;
    }
    if (sub == 0) {
        float* dst = g_S + (long)node * 192 + r * HD + q;
        *(float4*)dst = make_float4(a0[0], a0[1], a0[2], a0[3]);
        *(float4*)(dst + 4) = make_float4(a0[4], a0[5], a0[6], a0[7]);
    }
}

// layer-2 gather from fp32 h1: 16 thr per node, MLP=4
__global__ void k_gather(const float* __restrict__ h, int nLimit) {
    const int r = blockIdx.y;
    int node = blockIdx.x * 16 + (threadIdx.x >> 4);
    if (node >= nLimit) return;
    const int q = (threadIdx.x & 15) << 2;
    const int b = g_off[r][node], e2 = g_off[r][node + 1];
    const int* es = g_esrc[r];
    float4 a0 = make_float4(0.f, 0.f, 0.f, 0.f);
    float4 a1 = a0, a2 = a0, a3 = a0;
    int i = b;
    for (; i + 4 <= e2; i += 4) {
        int s0 = __ldg(es + i), s1 = __ldg(es + i + 1);
        int s2 = __ldg(es + i + 2), s3 = __ldg(es + i + 3);
        float4 v0 = *(const float4*)(h + (long)s0 * HD + q);
        float4 v1 = *(const float4*)(h + (long)s1 * HD + q);
        float4 v2 = *(const float4*)(h + (long)s2 * HD + q);
        float4 v3 = *(const float4*)(h + (long)s3 * HD + q);
        a0.x += v0.x; a0.y += v0.y; a0.z += v0.z; a0.w += v0.w;
        a1.x += v1.x; a1.y += v1.y; a1.z += v1.z; a1.w += v1.w;
        a2.x += v2.x; a2.y += v2.y; a2.z += v2.z; a2.w += v2.w;
        a3.x += v3.x; a3.y += v3.y; a3.z += v3.z; a3.w += v3.w;
    }
    for (; i < e2; i++) {
        float4 v = *(const float4*)(h + (long)__ldg(es + i) * HD + q);
        a0.x += v.x; a0.y += v.y; a0.z += v.z; a0.w += v.w;
    }
    a0.x += a1.x + a2.x + a3.x;
    a0.y += a1.y + a2.y + a3.y;
    a0.z += a1.z + a2.z + a3.z;
    a0.w += a1.w + a2.w + a3.w;
    float inv = (e2 > b) ? 1.f / (float)(e2 - b) : 1.f;
    a0.x *= inv; a0.y *= inv; a0.z *= inv; a0.w *= inv;
    *(float4*)(g_S + (long)node * 192 + r * HD + q) = a0;
}

__global__ void k_final(const float* __restrict__ W, const float* __restrict__ bias,
                        const float* __restrict__ noise) {
    __shared__ float sW[HD * HD];
    __shared__ float sS[4 * HD];
    for (int i = threadIdx.x; i < HD * HD; i += blockDim.x) sW[i] = W[i];
    __syncthreads();
    const int j = threadIdx.x & 63;
    const int ln = threadIdx.x >> 6;
    for (int n0 = blockIdx.x * 4; n0 < SSED; n0 += gridDim.x * 4) {
        int n = n0 + ln;
        sS[ln * HD + j] = g_h2[(long)n * HD + j];
        __syncthreads();
        float acc = bias[j];
#pragma unroll
        for (int k = 0; k < HD; k++)
            acc = fmaf(sS[ln * HD + k], sW[k * HD + j], acc);
        float v = (acc > 0.f) ? acc : 0.01f * acc;
        g_hsh[(long)n * HD + j] = __float2half_rn(v + noise[(long)n * HD + j]);
        __syncthreads();
    }
}

// ---------------- common asm helpers ----------------------------------------
__device__ __forceinline__ void cp16(void* smem, const void* gmem, bool valid) {
    unsigned s = (unsigned)__cvta_generic_to_shared(smem);
    int sz = valid ? 16 : 0;
    asm volatile("cp.async.cg.shared.global [%0], [%1], 16, %2;"
                 :: "r"(s), "l"(gmem), "r"(sz) : "memory");
}
__device__ __forceinline__ unsigned tf32(float f) {
    unsigned u;
    asm("cvt.rna.tf32.f32 %0, %1;" : "=r"(u) : "f"(f));
    return u;
}
__device__ __forceinline__ void mma8(float* c, const unsigned* a, const unsigned* b) {
    asm volatile("mma.sync.aligned.m16n8k8.row.col.f32.tf32.tf32.f32 "
                 "{%0,%1,%2,%3}, {%4,%5,%6,%7}, {%8,%9}, {%0,%1,%2,%3};"
                 : "+f"(c[0]), "+f"(c[1]), "+f"(c[2]), "+f"(c[3])
                 : "r"(a[0]), "r"(a[1]), "r"(a[2]), "r"(a[3]), "r"(b[0]), "r"(b[1]));
}
__device__ __forceinline__ void mma16h(float* c, const unsigned* a, const unsigned* b) {
    asm volatile("mma.sync.aligned.m16n8k16.row.col.f32.f16.f16.f32 "
                 "{%0,%1,%2,%3}, {%4,%5,%6,%7}, {%8,%9}, {%0,%1,%2,%3};"
                 : "+f"(c[0]), "+f"(c[1]), "+f"(c[2]), "+f"(c[3])
                 : "r"(a[0]), "r"(a[1]), "r"(a[2]), "r"(a[3]), "r"(b[0]), "r"(b[1]));
}
__device__ __forceinline__ void ldsm_x4(unsigned& r0, unsigned& r1, unsigned& r2,
                                        unsigned& r3, const void* p) {
    unsigned a = (unsigned)__cvta_generic_to_shared(p);
    asm volatile("ldmatrix.sync.aligned.m8n8.x4.shared.b16 {%0,%1,%2,%3}, [%4];"
                 : "=r"(r0), "=r"(r1), "=r"(r2), "=r"(r3) : "r"(a));
}
__device__ __forceinline__ void ldsm_x4t(unsigned& r0, unsigned& r1, unsigned& r2,
                                         unsigned& r3, const void* p) {
    unsigned a = (unsigned)__cvta_generic_to_shared(p);
    asm volatile("ldmatrix.sync.aligned.m8n8.x4.trans.shared.b16 {%0,%1,%2,%3}, [%4];"
                 : "=r"(r0), "=r"(r1), "=r"(r2), "=r"(r3) : "r"(a));
}

// ---------------- fp16 tensor-core GEMM (128x128 CTA, 64x32 warp, BK=32) ----
template <int ACT, int HOUT>
__global__ void __launch_bounds__(256, 2)
k_hgemm(const __half* __restrict__ Aall, const __half* __restrict__ Ball,
        const float* __restrict__ biasAll, void* __restrict__ Call,
        int M, int N, int K, long sA, long sB, long sBias, long sC, int ldc) {
    const int r = blockIdx.z;
    const __half* A = Aall + (long)r * sA;
    const __half* B = Ball + (long)r * sB;
    const float* bias = biasAll + (long)r * sBias;

    __shared__ __half As[2][128][40];
    __shared__ __half Bs[2][32][136];

    const int t = threadIdx.x;
    const int lane = t & 31;
    const int warp = t >> 5;
    const int wm = (warp >> 2) * 64;
    const int wn = (warp & 3) * 32;
    const long bm = (long)blockIdx.y * 128;
    const int bn = blockIdx.x * 128;

    const int aRow = t >> 1;
    const int aCol = (t & 1) << 4;
    const int bRow = t >> 3;
    const int bCol = (t & 7) << 4;
    const bool bv0 = (bn + bCol) < N;
    const bool bv1 = (bn + bCol + 8) < N;
    const int bc0 = bv0 ? bn + bCol : 0;
    const int bc1 = bv1 ? bn + bCol + 8 : 0;

    const int gid = lane >> 2;
    const int tig = lane & 3;

    float acc[4][4][4];
#pragma unroll
    for (int i = 0; i < 4; i++)
#pragma unroll
        for (int j = 0; j < 4; j++)
#pragma unroll
            for (int c = 0; c < 4; c++) acc[i][j][c] = 0.f;

    const int KT = K / 32;

    {
        cp16(&As[0][aRow][aCol], A + (bm + aRow) * (long)K + aCol, true);
        cp16(&As[0][aRow][aCol + 8], A + (bm + aRow) * (long)K + aCol + 8, true);
        cp16(&Bs[0][bRow][bCol], B + (long)bRow * N + bc0, bv0);
        cp16(&Bs[0][bRow][bCol + 8], B + (long)bRow * N + bc1, bv1);
        asm volatile("cp.async.commit_group;" ::: "memory");
        asm volatile("cp.async.wait_group 0;" ::: "memory");
        __syncthreads();
    }

    const int aFragRow = lane & 15;
    const int aFragCol = (lane >> 4) << 3;
    const int bFragRow = lane & 15;
    const int bFragCol = (lane >> 4) << 3;

    for (int kt = 0; kt < KT; kt++) {
        const int cb = kt & 1, nb = (kt + 1) & 1;
        if (kt + 1 < KT) {
            long ko = (long)(kt + 1) * 32;
            cp16(&As[nb][aRow][aCol], A + (bm + aRow) * (long)K + ko + aCol, true);
            cp16(&As[nb][aRow][aCol + 8], A + (bm + aRow) * (long)K + ko + aCol + 8, true);
            cp16(&Bs[nb][bRow][bCol], B + (ko + bRow) * (long)N + bc0, bv0);
            cp16(&Bs[nb][bRow][bCol + 8], B + (ko + bRow) * (long)N + bc1, bv1);
            asm volatile("cp.async.commit_group;" ::: "memory");
        }
#pragma unroll
        for (int kk = 0; kk < 2; kk++) {
            const int k0 = kk * 16;
            unsigned a[4][4], b[4][2];
#pragma unroll
            for (int tm = 0; tm < 4; tm++)
                ldsm_x4(a[tm][0], a[tm][1], a[tm][2], a[tm][3],
                        &As[cb][wm + tm * 16 + aFragRow][k0 + aFragCol]);
#pragma unroll
            for (int tn2 = 0; tn2 < 2; tn2++)
                ldsm_x4t(b[tn2 * 2][0], b[tn2 * 2][1], b[tn2 * 2 + 1][0], b[tn2 * 2 + 1][1],
                         &Bs[cb][k0 + bFragRow][wn + tn2 * 16 + bFragCol]);
#pragma unroll
            for (int tm = 0; tm < 4; tm++)
#pragma unroll
                for (int tn = 0; tn < 4; tn++)
                    mma16h(acc[tm][tn], a[tm], b[tn]);
        }
        if (kt + 1 < KT)
            asm volatile("cp.async.wait_group 0;" ::: "memory");
        __syncthreads();
    }

#pragma unroll
    for (int tm = 0; tm < 4; tm++) {
        long row0 = bm + wm + tm * 16 + gid;
#pragma unroll
        for (int tn = 0; tn < 4; tn++) {
            int col = bn + wn + tn * 8 + tig * 2;
            if (col < N) {
                float bs0 = bias[col], bs1 = bias[col + 1];
#pragma unroll
                for (int h = 0; h < 2; h++) {
                    long row = row0 + h * 8;
                    float u0 = acc[tm][tn][h * 2 + 0] + bs0;
                    float u1 = acc[tm][tn][h * 2 + 1] + bs1;
                    if (ACT == 1) { u0 = fmaxf(u0, 0.f); u1 = fmaxf(u1, 0.f); }
                    else if (ACT == 2) { u0 = (u0 > 0.f) ? u0 : 0.01f * u0;
                                         u1 = (u1 > 0.f) ? u1 : 0.01f * u1; }
                    else { u0 = tanhf(u0); u1 = tanhf(u1); }
                    if (HOUT) {
                        __half* Cp = (__half*)Call + (long)r * sC;
                        *(__half2*)(Cp + row * ldc + col) = __floats2half2_rn(u0, u1);
                    } else {
                        float* Cp = (float*)Call + (long)r * sC;
                        Cp[row * ldc + col] = u0;
                        Cp[row * ldc + col + 1] = u1;
                    }
                }
            }
        }
    }
}

// ---------------- TF32 tensor GEMM (conv combines) --------------------------
template <int ACT>
__global__ void __launch_bounds__(256, 2)
k_tgemm(const float* __restrict__ Aall, const float* __restrict__ Ball,
        const float* __restrict__ biasAll, float* __restrict__ Call,
        int M, int N, int K, long sA, long sB, long sBias, long sC, int ldc) {
    const int r = blockIdx.z;
    const float* A = Aall + (long)r * sA;
    const float* B = Ball + (long)r * sB;
    const float* bias = biasAll + (long)r * sBias;
    float* C = Call + (long)r * sC;

    __shared__ float As[2][128][20];
    __shared__ float Bs[2][16][136];

    const int t = threadIdx.x;
    const int lane = t & 31;
    const int warp = t >> 5;
    const int wm = (warp >> 2) * 64;
    const int wn = (warp & 3) * 32;
    const long bm = (long)blockIdx.y * 128;
    const int bn = blockIdx.x * 128;

    const int aRow = t >> 2;
    const int aCol = (t & 3) << 2;
    const int bRow = t >> 5;
    const int bCol = (t & 31) << 2;
    const bool bValid = (bn + bCol) < N;
    const int bnc = bValid ? bn + bCol : 0;

    const int gid = lane >> 2;
    const int tig = lane & 3;

    float acc[4][4][4];
#pragma unroll
    for (int i = 0; i < 4; i++)
#pragma unroll
        for (int j = 0; j < 4; j++)
#pragma unroll
            for (int c = 0; c < 4; c++) acc[i][j][c] = 0.f;

    const int KT = K / 16;

    {
        cp16(&As[0][aRow][aCol], A + (bm + aRow) * (long)K + aCol, true);
        cp16(&As[0][aRow + 64][aCol], A + (bm + aRow + 64) * (long)K + aCol, true);
        cp16(&Bs[0][bRow][bCol], B + (long)bRow * N + bnc, bValid);
        cp16(&Bs[0][bRow + 8][bCol], B + (long)(bRow + 8) * N + bnc, bValid);
        asm volatile("cp.async.commit_group;" ::: "memory");
        asm volatile("cp.async.wait_group 0;" ::: "memory");
        __syncthreads();
    }

    for (int kt = 0; kt < KT; kt++) {
        const int cb = kt & 1, nb = (kt + 1) & 1;
        if (kt + 1 < KT) {
            long ko = (long)(kt + 1) * 16;
            cp16(&As[nb][aRow][aCol], A + (bm + aRow) * (long)K + ko + aCol, true);
            cp16(&As[nb][aRow + 64][aCol], A + (bm + aRow + 64) * (long)K + ko + aCol, true);
            cp16(&Bs[nb][bRow][bCol], B + (ko + bRow) * (long)N + bnc, bValid);
            cp16(&Bs[nb][bRow + 8][bCol], B + (ko + bRow + 8) * (long)N + bnc, bValid);
            asm volatile("cp.async.commit_group;" ::: "memory");
        }
#pragma unroll
        for (int k8 = 0; k8 < 2; k8++) {
            const int k0 = k8 * 8;
            unsigned a[4][4], b[4][2];
#pragma unroll
            for (int tm = 0; tm < 4; tm++) {
                int m = wm + tm * 16 + gid;
                a[tm][0] = tf32(As[cb][m][k0 + tig]);
                a[tm][1] = tf32(As[cb][m + 8][k0 + tig]);
                a[tm][2] = tf32(As[cb][m][k0 + tig + 4]);
                a[tm][3] = tf32(As[cb][m + 8][k0 + tig + 4]);
            }
#pragma unroll
            for (int tn = 0; tn < 4; tn++) {
                int n = wn + tn * 8 + gid;
                b[tn][0] = tf32(Bs[cb][k0 + tig][n]);
                b[tn][1] = tf32(Bs[cb][k0 + tig + 4][n]);
            }
#pragma unroll
            for (int tm = 0; tm < 4; tm++)
#pragma unroll
                for (int tn = 0; tn < 4; tn++)
                    mma8(acc[tm][tn], a[tm], b[tn]);
        }
        if (kt + 1 < KT)
            asm volatile("cp.async.wait_group 0;" ::: "memory");
        __syncthreads();
    }

#pragma unroll
    for (int tm = 0; tm < 4; tm++) {
        long row0 = bm + wm + tm * 16 + gid;
#pragma unroll
        for (int tn = 0; tn < 4; tn++) {
            int col = bn + wn + tn * 8 + tig * 2;
            if (col < N) {
                float bs0 = bias[col], bs1 = bias[col + 1];
#pragma unroll
                for (int h = 0; h < 2; h++) {
                    long row = row0 + h * 8;
                    float u0 = acc[tm][tn][h * 2 + 0] + bs0;
                    float u1 = acc[tm][tn][h * 2 + 1] + bs1;
                    if (ACT == 1) { u0 = fmaxf(u0, 0.f); u1 = fmaxf(u1, 0.f); }
                    else if (ACT == 2) { u0 = (u0 > 0.f) ? u0 : 0.01f * u0;
                                         u1 = (u1 > 0.f) ? u1 : 0.01f * u1; }
                    else { u0 = tanhf(u0); u1 = tanhf(u1); }
                    C[row * ldc + col] = u0;
                    C[row * ldc + col + 1] = u1;
                }
            }
        }
    }
}

// pred_missing head
__global__ void k_dw3(const float* __restrict__ z, const float* __restrict__ W,
                      const float* __restrict__ b, float* __restrict__ out) {
    int i = blockIdx.x * blockDim.x + threadIdx.x;
    if (i >= 3 * SSED) return;
    int r = i / SSED;
    int s = i % SSED;
    const float* zz = z + ((long)r * SSED + s) * 32;
    const float* w = W + r * 32;
    float acc = b[r];
#pragma unroll
    for (int k = 0; k < 32; k++) acc = fmaf(zz[k], w[k], acc);
    out[((long)r * SSED + s) * 321] = fmaxf(acc, 0.f);
}

// ---------------- host launch ----------------------------------------------
extern "C" void kernel_launch(void* const* d_in, const int* in_sizes, int n_in,
                              void* d_out, int out_size) {
    static const int MAP_DICT[27] = {0,1,2,3,4,5,6,7,8,9,10,11,12,13,14,15,16,17,18,19,20,21,22,23,24,25,26};
    static const int MAP_SIG[27]  = {0,1,20,21,22,23,24,25,26,2,3,4,5,6,7,8,9,10,11,12,13,14,15,16,17,18,19};
    static const int MAP_ALPHA[27]= {26,21,22,23,12,24,13,25,14,0,3,1,4,2,5,6,9,7,10,8,11,15,18,16,19,17,20};
    const int* MAP = MAP_DICT;
    if (n_in >= 3) {
        if (in_sizes[2] == 12288) MAP = MAP_SIG;
        else if (in_sizes[2] == 4096) MAP = MAP_ALPHA;
    }

    const float* x     = (const float*)d_in[MAP[0]];
    const float* noise = (const float*)d_in[MAP[1]];
    const int* src[3]  = {(const int*)d_in[MAP[3]], (const int*)d_in[MAP[5]], (const int*)d_in[MAP[7]]};
    const int* dst[3]  = {(const int*)d_in[MAP[4]], (const int*)d_in[MAP[6]], (const int*)d_in[MAP[8]]};
    const float* Wc1   = (const float*)d_in[MAP[9]];
    const float* bc1   = (const float*)d_in[MAP[10]];
    const float* Wc2   = (const float*)d_in[MAP[11]];
    const float* bc2   = (const float*)d_in[MAP[12]];
    const float* Wlin  = (const float*)d_in[MAP[13]];
    const float* blin  = (const float*)d_in[MAP[14]];
    const float* dW1   = (const float*)d_in[MAP[15]];
    const float* db1   = (const float*)d_in[MAP[16]];
    const float* dW2   = (const float*)d_in[MAP[17]];
    const float* db2   = (const float*)d_in[MAP[18]];
    const float* dW3   = (const float*)d_in[MAP[19]];
    const float* db3   = (const float*)d_in[MAP[20]];
    const float* fW1   = (const float*)d_in[MAP[21]];
    const float* fb1   = (const float*)d_in[MAP[22]];
    const float* fW2   = (const float*)d_in[MAP[23]];
    const float* fb2   = (const float*)d_in[MAP[24]];
    const float* fW3   = (const float*)d_in[MAP[25]];
    const float* fb3   = (const float*)d_in[MAP[26]];
    float* out = (float*)d_out;

    float *pS, *pH1, *pH2, *pZ2;
    __half *pXh, *pHsh, *pY1h, *pY2h, *pWd1h, *pWd2h, *pWf1h, *pWf2h, *pWf3h;
    cudaGetSymbolAddress((void**)&pS,    g_S);
    cudaGetSymbolAddress((void**)&pH1,   g_h1);
    cudaGetSymbolAddress((void**)&pH2,   g_h2);
    cudaGetSymbolAddress((void**)&pZ2,   g_zd2);
    cudaGetSymbolAddress((void**)&pXh,   g_xh);
    cudaGetSymbolAddress((void**)&pHsh,  g_hsh);
    cudaGetSymbolAddress((void**)&pY1h,  g_y1h);
    cudaGetSymbolAddress((void**)&pY2h,  g_y2h);
    cudaGetSymbolAddress((void**)&pWd1h, g_wd1h);
    cudaGetSymbolAddress((void**)&pWd2h, g_wd2h);
    cudaGetSymbolAddress((void**)&pWf1h, g_wf1h);
    cudaGetSymbolAddress((void**)&pWf2h, g_wf2h);
    cudaGetSymbolAddress((void**)&pWf3h, g_wf3h);

    // ----- fused conversions + degree count (g_cur pre-zeroed) -----
    k_convert<<<(int)((CVT_TOT + 255) / 256), 256>>>(x, dW1, dW2, fW1, fW2, fW3,
                                                     dst[0], dst[1], dst[2]);

    // ----- CSR scan + fill -----
    k_scan<<<3, 1024>>>();
    {
        dim3 g((EE + 255) / 256, 3);
        k_fill<<<g, 256>>>(src[0], dst[0], src[1], dst[1], src[2], dst[2]);
    }

    // ----- conv layer 1 (fp16 gather, MLP=8 via split groups; re-zeroes g_cur) -----
    {
        dim3 g((NN + 15) / 16, 3);
        k_gather_h<<<g, 256>>>(pXh);
    }
    k_tgemm<1><<<dim3(1, NNP / 128, 1), 256>>>(pS, Wc1, bc1, pH1,
                                               NNP, 64, 192, 0, 0, 0, 0, 64);

    // ----- conv layer 2 -----
    {
        dim3 g(SSED / 16, 3);
        k_gather<<<g, 256>>>(pH1, SSED);
    }
    k_tgemm<1><<<dim3(1, SSED / 128, 1), 256>>>(pS, Wc2, bc2, pH2,
                                                SSED, 64, 192, 0, 0, 0, 0, 64);

    // ----- final linear (fp16 hs) -----
    k_final<<<2048, 256>>>(Wlin, blin, noise);

    // ----- decoder: pred_missing -----
    dim3 g1(2, SSED / 128, 3);
    k_hgemm<2, 1><<<g1, 256>>>(pHsh, pWd1h, db1, pY1h, SSED, 256, 64,
                               0, (long)64 * 256, 256, (long)SSED * 256, 256);
    dim3 g2(1, SSED / 128, 3);
    k_hgemm<2, 0><<<g2, 256>>>(pY1h, pWd2h, db2, pZ2, SSED, 32, 256,
                               (long)SSED * 256, (long)256 * 32, 32,
                               (long)SSED * 32, 32);
    k_dw3<<<(3 * SSED + 255) / 256, 256>>>(pZ2, dW3, db3, out);

    // ----- decoder: pred_feat -----
    k_hgemm<1, 1><<<g1, 256>>>(pHsh, pWf1h, fb1, pY1h, SSED, 256, 64,
                               0, (long)64 * 256, 256, (long)SSED * 256, 256);
    dim3 g3(16, SSED / 128, 3);
    k_hgemm<1, 1><<<g3, 256>>>(pY1h, pWf2h, fb2, pY2h, SSED, 2048, 256,
                               (long)SSED * 256, (long)256 * 2048, 2048,
                               (long)SSED * 2048, 2048);
    dim3 g4(3, SSED / 128, 3);
    k_hgemm<3, 0><<<g4, 256>>>(pY2h, pWf3h, fb3, out + 1, SSED, 320, 2048,
                               (long)SSED * 2048, (long)2048 * 320, 320,
                               (long)SSED * 321, 321);
}